// round 3
// baseline (speedup 1.0000x reference)
#include <cuda_runtime.h>
#include <cuda_bf16.h>
#include <math.h>
#include <stdint.h>

// Problem constants
#define L_   4
#define DM_  768
#define DI_  1536
#define DS_  16
#define DR_  48
#define KC_  4
#define V_   32000
#define B_   2
#define S_   2048
#define BS_  (B_*S_)       // 4096 tokens
#define XZ_  (2*DI_)       // 3072
#define DBC_ (DR_+2*DS_)   // 80

// ---------------- scratch (static device memory; no allocations) ----------------
__device__ float g_h   [BS_*DM_];
__device__ float g_xn  [BS_*DM_];
__device__ float g_xz  [BS_*XZ_];
__device__ float g_xc  [BS_*DI_];
__device__ float g_dbc [BS_*DBC_];
__device__ float g_dt  [BS_*DI_];
__device__ float g_y   [BS_*DI_];
__device__ float g_comb[BS_*2*DM_];
__device__ float g_rownll[BS_];

// ---------------- embedding gather (optionally sequence-reversed) ----------------
__global__ void embed_k(const int* __restrict__ ids, const float* __restrict__ emb,
                        float* __restrict__ h, int flip) {
    int r = blockIdx.x;
    int b = r / S_, s = r % S_;
    int s2 = flip ? (S_ - 1 - s) : s;
    int tok = ids[b * S_ + s2];
    const float* e = emb + (size_t)tok * DM_;
    float* o = h + (size_t)r * DM_;
    for (int i = threadIdx.x; i < DM_; i += blockDim.x) o[i] = e[i];
}

// ---------------- RMSNorm (optionally writing flipped / offset / strided) ----------------
__global__ void rms_k(const float* __restrict__ x, const float* __restrict__ w,
                      float* __restrict__ out, int ldo, int off, int flip) {
    int r = blockIdx.x;
    const float* xr = x + (size_t)r * DM_;
    float ss = 0.f;
    for (int i = threadIdx.x; i < DM_; i += blockDim.x) { float v = xr[i]; ss += v * v; }
    __shared__ float red[32];
    #pragma unroll
    for (int o = 16; o; o >>= 1) ss += __shfl_xor_sync(~0u, ss, o);
    if ((threadIdx.x & 31) == 0) red[threadIdx.x >> 5] = ss;
    __syncthreads();
    if (threadIdx.x < 32) {
        float v = (threadIdx.x < (blockDim.x >> 5)) ? red[threadIdx.x] : 0.f;
        #pragma unroll
        for (int o = 16; o; o >>= 1) v += __shfl_xor_sync(~0u, v, o);
        if (threadIdx.x == 0) red[0] = v;
    }
    __syncthreads();
    float scale = rsqrtf(red[0] / (float)DM_ + 1e-5f);
    int ro = r;
    if (flip) { int b = r / S_, s = r % S_; ro = b * S_ + (S_ - 1 - s); }
    float* o = out + (size_t)ro * ldo + off;
    for (int i = threadIdx.x; i < DM_; i += blockDim.x) o[i] = xr[i] * scale * w[i];
}

// ---------------- depthwise causal conv (kernel 4) + SiLU ----------------
__global__ void conv_k(const float* __restrict__ xz, const float* __restrict__ cw,
                       const float* __restrict__ cb, float* __restrict__ xc) {
    int idx = blockIdx.x * blockDim.x + threadIdx.x;
    if (idx >= BS_ * DI_) return;
    int d = idx % DI_;
    int r = idx / DI_;
    int s = r % S_;
    float acc = cb[d];
    #pragma unroll
    for (int k = 0; k < KC_; k++) {
        int sp = s - (KC_ - 1) + k;
        if (sp >= 0) acc += xz[(size_t)(r - s + sp) * XZ_ + d] * cw[d * KC_ + k];
    }
    float sig = 1.f / (1.f + expf(-acc));
    xc[idx] = acc * sig;
}

// ================= tensor-core GEMM (bf16-split "3xBF16", fp32 accuracy class) =================
// C[M,N] = A[M,K] * B[N,K]^T, row-major, K contiguous. M % 128 == 0, K % 16 == 0 (all call sites).
// Optional per-col bias, softplus (act=1), accumulate into C (accum=1).
#define BM 128
#define BN 128
#define BKC 32

__device__ __forceinline__ void mma_bf16(float* c, const uint32_t* a, const uint32_t* b) {
    asm volatile(
        "mma.sync.aligned.m16n8k16.row.col.f32.bf16.bf16.f32 "
        "{%0,%1,%2,%3}, {%4,%5,%6,%7}, {%8,%9}, {%0,%1,%2,%3};"
        : "+f"(c[0]), "+f"(c[1]), "+f"(c[2]), "+f"(c[3])
        : "r"(a[0]), "r"(a[1]), "r"(a[2]), "r"(a[3]), "r"(b[0]), "r"(b[1]));
}

__device__ __forceinline__ void ldsm4(uint32_t* r, uint32_t addr) {
    asm volatile("ldmatrix.sync.aligned.m8n8.x4.shared.b16 {%0,%1,%2,%3}, [%4];"
                 : "=r"(r[0]), "=r"(r[1]), "=r"(r[2]), "=r"(r[3]) : "r"(addr));
}

__global__ __launch_bounds__(256, 1) void gemm_tc(
    const float* __restrict__ A, int lda,
    const float* __restrict__ Bm, int ldb,
    float* __restrict__ C, int ldc,
    int M, int N, int K,
    const float* __restrict__ bias, int act, int accum)
{
    // stride 40 bf16 = 80 bytes: conflict-free for the LDSM row pattern
    __shared__ __nv_bfloat16 As_hi[BM][BKC + 8];
    __shared__ __nv_bfloat16 As_lo[BM][BKC + 8];
    __shared__ __nv_bfloat16 Bs_hi[BN][BKC + 8];
    __shared__ __nv_bfloat16 Bs_lo[BN][BKC + 8];

    const int tid = threadIdx.x;
    const int lane = tid & 31, warp = tid >> 5;
    const int wm = (warp >> 2) * 64;   // 0 / 64
    const int wn = (warp & 3) * 32;    // 0,32,64,96
    const int bm0 = blockIdx.x * BM;   // M tile (fast dim -> weight panel L2 reuse)
    const int bn0 = blockIdx.y * BN;

    float acc[4][4][4];
    #pragma unroll
    for (int i = 0; i < 4; i++)
        #pragma unroll
        for (int j = 0; j < 4; j++)
            #pragma unroll
            for (int f = 0; f < 4; f++) acc[i][j][f] = 0.f;

    // gmem staging: 1024 float4 per matrix per chunk; 4 per thread
    float4 pa[4], pb[4];
    const int ld_r[4] = { (tid + 0) >> 3, (tid + 256) >> 3, (tid + 512) >> 3, (tid + 768) >> 3 };
    const int ld_c = (tid & 7) * 4;

    auto load_chunk = [&](int k0) {
        #pragma unroll
        for (int i = 0; i < 4; i++) {
            int r = ld_r[i];
            bool kok = (k0 + ld_c) < K;
            pa[i] = kok ? *(const float4*)(A + (size_t)(bm0 + r) * lda + k0 + ld_c)
                        : make_float4(0.f, 0.f, 0.f, 0.f);
            bool bok = kok && (bn0 + r) < N;
            pb[i] = bok ? *(const float4*)(Bm + (size_t)(bn0 + r) * ldb + k0 + ld_c)
                        : make_float4(0.f, 0.f, 0.f, 0.f);
        }
    };
    auto store_chunk = [&]() {
        #pragma unroll
        for (int i = 0; i < 4; i++) {
            int r = ld_r[i];
            float v[4] = { pa[i].x, pa[i].y, pa[i].z, pa[i].w };
            float w[4] = { pb[i].x, pb[i].y, pb[i].z, pb[i].w };
            #pragma unroll
            for (int j = 0; j < 4; j++) {
                __nv_bfloat16 h = __float2bfloat16(v[j]);
                As_hi[r][ld_c + j] = h;
                As_lo[r][ld_c + j] = __float2bfloat16(v[j] - __bfloat162float(h));
                __nv_bfloat16 g = __float2bfloat16(w[j]);
                Bs_hi[r][ld_c + j] = g;
                Bs_lo[r][ld_c + j] = __float2bfloat16(w[j] - __bfloat162float(g));
            }
        }
    };

    // ldmatrix lane addressing
    const int a_row = wm + (lane & 15);
    const int a_koff = (lane >> 4) * 8;
    const int b_row = wn + (lane & 7) + ((lane >> 4) << 3);
    const int b_koff = ((lane >> 3) & 1) * 8;

    const int nchunks = (K + BKC - 1) / BKC;
    load_chunk(0);
    store_chunk();
    __syncthreads();

    for (int c = 1; c <= nchunks; c++) {
        if (c < nchunks) load_chunk(c * BKC);   // overlap gmem latency with MMA

        #pragma unroll
        for (int ks = 0; ks < BKC; ks += 16) {
            uint32_t ah[4][4], al[4][4], bh[4][2], bl[4][2];
            #pragma unroll
            for (int im = 0; im < 4; im++) {
                uint32_t adr_h = (uint32_t)__cvta_generic_to_shared(&As_hi[a_row + im * 16][ks + a_koff]);
                uint32_t adr_l = (uint32_t)__cvta_generic_to_shared(&As_lo[a_row + im * 16][ks + a_koff]);
                ldsm4(ah[im], adr_h);
                ldsm4(al[im], adr_l);
            }
            #pragma unroll
            for (int ib = 0; ib < 2; ib++) {
                uint32_t rh[4], rl[4];
                uint32_t adr_h = (uint32_t)__cvta_generic_to_shared(&Bs_hi[b_row + ib * 16][ks + b_koff]);
                uint32_t adr_l = (uint32_t)__cvta_generic_to_shared(&Bs_lo[b_row + ib * 16][ks + b_koff]);
                ldsm4(rh, adr_h);
                ldsm4(rl, adr_l);
                bh[2 * ib][0] = rh[0]; bh[2 * ib][1] = rh[1];
                bh[2 * ib + 1][0] = rh[2]; bh[2 * ib + 1][1] = rh[3];
                bl[2 * ib][0] = rl[0]; bl[2 * ib][1] = rl[1];
                bl[2 * ib + 1][0] = rl[2]; bl[2 * ib + 1][1] = rl[3];
            }
            #pragma unroll
            for (int im = 0; im < 4; im++)
                #pragma unroll
                for (int in = 0; in < 4; in++) {
                    mma_bf16(acc[im][in], ah[im], bh[in]);   // hi*hi
                    mma_bf16(acc[im][in], ah[im], bl[in]);   // hi*lo
                    mma_bf16(acc[im][in], al[im], bh[in]);   // lo*hi
                }
        }
        __syncthreads();
        if (c < nchunks) {
            store_chunk();
            __syncthreads();
        }
    }

    // epilogue
    #pragma unroll
    for (int im = 0; im < 4; im++) {
        int row0 = bm0 + wm + im * 16 + (lane >> 2);
        #pragma unroll
        for (int in = 0; in < 4; in++) {
            int col = bn0 + wn + in * 8 + 2 * (lane & 3);
            if (col >= N) continue;
            #pragma unroll
            for (int half = 0; half < 2; half++) {   // rows row0 and row0+8
                int row = row0 + half * 8;
                float v0 = acc[im][in][half * 2 + 0];
                float v1 = acc[im][in][half * 2 + 1];
                if (bias) { v0 += bias[col]; v1 += bias[col + 1]; }
                if (act == 1) {
                    v0 = (v0 > 20.f) ? v0 : log1pf(expf(v0));
                    v1 = (v1 > 20.f) ? v1 : log1pf(expf(v1));
                }
                float* cp = C + (size_t)row * ldc + col;
                if (accum) { v0 += cp[0]; v1 += cp[1]; }
                *(float2*)cp = make_float2(v0, v1);
            }
        }
    }
}

// ---------------- selective scan: one thread per (batch, channel) ----------------
__global__ void scan_k(const float* __restrict__ dt, const float* __restrict__ dbc,
                       const float* __restrict__ xc, const float* __restrict__ xz,
                       const float* __restrict__ Alog, const float* __restrict__ Dp,
                       float* __restrict__ y) {
    int t = blockIdx.x * blockDim.x + threadIdx.x;
    if (t >= B_ * DI_) return;
    int b = t / DI_, d = t % DI_;
    float a[DS_], h[DS_];
    #pragma unroll
    for (int n = 0; n < DS_; n++) { a[n] = -expf(Alog[d * DS_ + n]); h[n] = 0.f; }
    float Dpd = Dp[d];
    for (int s = 0; s < S_; s++) {
        size_t r = (size_t)b * S_ + s;
        float dtv = dt[r * DI_ + d];
        float xv  = xc[r * DI_ + d];
        float zv  = xz[r * XZ_ + DI_ + d];
        const float* bc = dbc + r * DBC_;
        float dx = dtv * xv;
        float yv = 0.f;
        #pragma unroll
        for (int n = 0; n < DS_; n++) {
            float e = expf(dtv * a[n]);
            h[n] = e * h[n] + dx * bc[DR_ + n];
            yv  += h[n] * bc[DR_ + DS_ + n];
        }
        yv += Dpd * xv;
        float sil = zv / (1.f + expf(-zv));
        y[r * DI_ + d] = yv * sil;
    }
}

// ---------------- per-row logsumexp + NLL ----------------
__global__ void loss_row_k(const float* __restrict__ logits, const int* __restrict__ labels,
                           float* __restrict__ rownll) {
    int r = blockIdx.x;
    const float* lr = logits + (size_t)r * V_;
    __shared__ float red[32];
    float m = -INFINITY;
    for (int i = threadIdx.x; i < V_; i += blockDim.x) m = fmaxf(m, lr[i]);
    #pragma unroll
    for (int o = 16; o; o >>= 1) m = fmaxf(m, __shfl_xor_sync(~0u, m, o));
    if ((threadIdx.x & 31) == 0) red[threadIdx.x >> 5] = m;
    __syncthreads();
    if (threadIdx.x == 0) { float v = red[0]; for (int i = 1; i < 8; i++) v = fmaxf(v, red[i]); red[0] = v; }
    __syncthreads();
    m = red[0];
    __syncthreads();
    float sum = 0.f;
    for (int i = threadIdx.x; i < V_; i += blockDim.x) sum += expf(lr[i] - m);
    #pragma unroll
    for (int o = 16; o; o >>= 1) sum += __shfl_xor_sync(~0u, sum, o);
    if ((threadIdx.x & 31) == 0) red[threadIdx.x >> 5] = sum;
    __syncthreads();
    if (threadIdx.x == 0) {
        float v = 0.f;
        for (int i = 0; i < 8; i++) v += red[i];
        int lab = labels[r];
        float nll = 0.f;
        if (lab != -100) nll = (m + logf(v)) - lr[lab];
        rownll[r] = nll;
    }
}

// ---------------- deterministic final reduction ----------------
__global__ void loss_red_k(const float* __restrict__ rownll, const int* __restrict__ labels,
                           float* __restrict__ out) {
    __shared__ float rs[32]; __shared__ int rc[32];
    float s = 0.f; int c = 0;
    for (int i = threadIdx.x; i < BS_; i += blockDim.x) {
        s += rownll[i];
        if (labels[i] != -100) c++;
    }
    #pragma unroll
    for (int o = 16; o; o >>= 1) { s += __shfl_xor_sync(~0u, s, o); c += __shfl_xor_sync(~0u, c, o); }
    if ((threadIdx.x & 31) == 0) { rs[threadIdx.x >> 5] = s; rc[threadIdx.x >> 5] = c; }
    __syncthreads();
    if (threadIdx.x == 0) {
        float vs = 0.f; int vc = 0;
        for (int i = 0; i < 8; i++) { vs += rs[i]; vc += rc[i]; }
        if (vc < 1) vc = 1;
        *out = vs / (float)vc;
    }
}

// ---------------- host orchestration ----------------
static inline void launch_gemm(const float* A, int lda, const float* Bm, int ldb,
                               float* C, int ldc, int M, int N, int K,
                               const float* bias, int act, int accum) {
    dim3 grid(M / BM, (N + BN - 1) / BN);   // M fastest: weight panel stays in L2
    gemm_tc<<<grid, 256>>>(A, lda, Bm, ldb, C, ldc, M, N, K, bias, act, accum);
}

extern "C" void kernel_launch(void* const* d_in, const int* in_sizes, int n_in,
                              void* d_out, int out_size) {
    const int* ids    = (const int*)d_in[0];
    const int* labels = (const int*)d_in[1];
    const float* P[2][12];
    for (int dir = 0; dir < 2; dir++)
        for (int j = 0; j < 12; j++)
            P[dir][j] = (const float*)d_in[2 + dir * 12 + j];
    const float* lm_w = (const float*)d_in[26];
    float* out = (float*)d_out;
    float* logits = out;

    float *h, *xn, *xz, *xc, *dbcp, *dt, *y, *comb, *rownll;
    cudaGetSymbolAddress((void**)&h,     g_h);
    cudaGetSymbolAddress((void**)&xn,    g_xn);
    cudaGetSymbolAddress((void**)&xz,    g_xz);
    cudaGetSymbolAddress((void**)&xc,    g_xc);
    cudaGetSymbolAddress((void**)&dbcp,  g_dbc);
    cudaGetSymbolAddress((void**)&dt,    g_dt);
    cudaGetSymbolAddress((void**)&y,     g_y);
    cudaGetSymbolAddress((void**)&comb,  g_comb);
    cudaGetSymbolAddress((void**)&rownll, g_rownll);

    for (int dir = 0; dir < 2; dir++) {
        const float* emb   = P[dir][0];
        const float* norm  = P[dir][1];
        const float* inw   = P[dir][2];
        const float* convw = P[dir][3];
        const float* convb = P[dir][4];
        const float* xpw   = P[dir][5];
        const float* dtw   = P[dir][6];
        const float* dtb   = P[dir][7];
        const float* Alog  = P[dir][8];
        const float* Dp    = P[dir][9];
        const float* outw  = P[dir][10];
        const float* fnorm = P[dir][11];

        embed_k<<<BS_, 256>>>(ids, emb, h, dir);

        for (int l = 0; l < L_; l++) {
            rms_k<<<BS_, 256>>>(h, norm + (size_t)l * DM_, xn, DM_, 0, 0);
            launch_gemm(xn, DM_, inw + (size_t)l * 2 * DI_ * DM_, DM_,
                        xz, XZ_, BS_, XZ_, DM_, nullptr, 0, 0);
            conv_k<<<(BS_ * DI_ + 255) / 256, 256>>>(xz, convw + (size_t)l * DI_ * KC_,
                                                     convb + (size_t)l * DI_, xc);
            launch_gemm(xc, DI_, xpw + (size_t)l * DBC_ * DI_, DI_,
                        dbcp, DBC_, BS_, DBC_, DI_, nullptr, 0, 0);
            launch_gemm(dbcp, DBC_, dtw + (size_t)l * DI_ * DR_, DR_,
                        dt, DI_, BS_, DI_, DR_, dtb + (size_t)l * DI_, 1, 0);
            scan_k<<<(B_ * DI_ + 127) / 128, 128>>>(dt, dbcp, xc, xz,
                                                    Alog + (size_t)l * DI_ * DS_,
                                                    Dp + (size_t)l * DI_, y);
            launch_gemm(y, DI_, outw + (size_t)l * DM_ * DI_, DI_,
                        h, DM_, BS_, DM_, DI_, nullptr, 0, 1);
        }
        rms_k<<<BS_, 256>>>(h, fnorm, comb, 2 * DM_, dir ? DM_ : 0, dir);
    }

    launch_gemm(comb, 2 * DM_, lm_w, 2 * DM_, logits, V_, BS_, V_, 2 * DM_, nullptr, 0, 0);

    loss_row_k<<<BS_, 256>>>(logits, labels, rownll);
    loss_red_k<<<1, 256>>>(rownll, labels, out + (out_size - 1));
}

// round 6
// speedup vs baseline: 1.3366x; 1.3366x over previous
#include <cuda_runtime.h>
#include <cuda_bf16.h>
#include <math.h>
#include <stdint.h>

#define L_   4
#define DM_  768
#define DI_  1536
#define DS_  16
#define DR_  48
#define KC_  4
#define V_   32000
#define B_   2
#define S_   2048
#define BS_  (B_*S_)
#define XZ_  (2*DI_)
#define DBC_ (DR_+2*DS_)   // 80

// ---------------- scratch ----------------
__device__ float g_h   [BS_*DM_];
__device__ float g_xz  [BS_*XZ_];
__device__ float g_xc  [BS_*DI_];
__device__ float g_dbc [BS_*DBC_];
__device__ float g_dt  [BS_*DI_];
__device__ float g_rownll[BS_];
// 3-section bf16-split operands.
// A-side layout: [hi(C) | lo(C) | hi(C)] ; B-side (weights): [hi(C) | hi(C) | lo(C)]
__device__ __nv_bfloat16 g_a3[(size_t)BS_*3*DI_];
__device__ __nv_bfloat16 g_d3[(size_t)BS_*3*DR_];
__device__ __nv_bfloat16 g_c3[(size_t)BS_*3*(2*DM_)];
__device__ __nv_bfloat16 g_w3[(size_t)V_*3*(2*DM_)];

__device__ __forceinline__ void split_bf(float v, __nv_bfloat16& h, __nv_bfloat16& l) {
    h = __float2bfloat16(v);
    l = __float2bfloat16(v - __bfloat162float(h));
}

__global__ void embed_k(const int* __restrict__ ids, const float* __restrict__ emb,
                        float* __restrict__ h, int flip) {
    int r = blockIdx.x;
    int b = r / S_, s = r % S_;
    int s2 = flip ? (S_ - 1 - s) : s;
    int tok = ids[b * S_ + s2];
    const float* e = emb + (size_t)tok * DM_;
    float* o = h + (size_t)r * DM_;
    for (int i = threadIdx.x; i < DM_; i += blockDim.x) o[i] = e[i];
}

// RMSNorm -> A-side 3-section bf16 [hi|lo|hi] (optionally flipped / col-offset into wider row)
__global__ void rms3_k(const float* __restrict__ x, const float* __restrict__ w,
                       __nv_bfloat16* __restrict__ o3, int Ctot, int off, int flip) {
    int r = blockIdx.x;
    const float* xr = x + (size_t)r * DM_;
    float ss = 0.f;
    for (int i = threadIdx.x; i < DM_; i += blockDim.x) { float v = xr[i]; ss += v * v; }
    __shared__ float red[32];
    #pragma unroll
    for (int o = 16; o; o >>= 1) ss += __shfl_xor_sync(~0u, ss, o);
    if ((threadIdx.x & 31) == 0) red[threadIdx.x >> 5] = ss;
    __syncthreads();
    if (threadIdx.x < 32) {
        float v = (threadIdx.x < (blockDim.x >> 5)) ? red[threadIdx.x] : 0.f;
        #pragma unroll
        for (int o = 16; o; o >>= 1) v += __shfl_xor_sync(~0u, v, o);
        if (threadIdx.x == 0) red[0] = v;
    }
    __syncthreads();
    float scale = rsqrtf(red[0] / (float)DM_ + 1e-5f);
    int ro = r;
    if (flip) { int b = r / S_, s = r % S_; ro = b * S_ + (S_ - 1 - s); }
    size_t base = (size_t)ro * 3 * Ctot + off;
    for (int i = threadIdx.x; i < DM_; i += blockDim.x) {
        float v = xr[i] * scale * w[i];
        __nv_bfloat16 hh, ll; split_bf(v, hh, ll);
        o3[base + i] = hh; o3[base + Ctot + i] = ll; o3[base + 2 * Ctot + i] = hh;
    }
}

// depthwise causal conv + SiLU -> fp32 + A-side 3-section [hi|lo|hi]
__global__ void conv3_k(const float* __restrict__ xz, const float* __restrict__ cw,
                        const float* __restrict__ cb, float* __restrict__ xc,
                        __nv_bfloat16* __restrict__ o3) {
    int idx = blockIdx.x * blockDim.x + threadIdx.x;
    if (idx >= BS_ * DI_) return;
    int d = idx % DI_;
    int r = idx / DI_;
    int s = r % S_;
    float acc = cb[d];
    #pragma unroll
    for (int k = 0; k < KC_; k++) {
        int sp = s - (KC_ - 1) + k;
        if (sp >= 0) acc += xz[(size_t)(r - s + sp) * XZ_ + d] * cw[d * KC_ + k];
    }
    float sig = 1.f / (1.f + expf(-acc));
    float v = acc * sig;
    xc[idx] = v;
    __nv_bfloat16 hh, ll; split_bf(v, hh, ll);
    size_t base = (size_t)r * 3 * DI_ + d;
    o3[base] = hh; o3[base + DI_] = ll; o3[base + 2 * DI_] = hh;
}

// fp32 [R,Cin] (row stride ldin) -> first Cout cols -> 3-section bf16 [R,3*Cout]
// wmode 0 (A-side): [hi | lo | hi]    wmode 1 (B-side): [hi | hi | lo]
__global__ void cvt3_k(const float* __restrict__ x, __nv_bfloat16* __restrict__ o3,
                       int ldin, int Cout, int n4, int wmode) {
    int i = blockIdx.x * blockDim.x + threadIdx.x;
    if (i >= n4) return;
    int e = i * 4;
    int r = e / Cout, c = e % Cout;
    float4 v = *(const float4*)(x + (size_t)r * ldin + c);
    __nv_bfloat16 h0, h1, h2, h3, l0, l1, l2, l3;
    split_bf(v.x, h0, l0); split_bf(v.y, h1, l1);
    split_bf(v.z, h2, l2); split_bf(v.w, h3, l3);
    size_t base = (size_t)r * 3 * Cout + c;
    __nv_bfloat162 H01(h0, h1), H23(h2, h3), L01(l0, l1), L23(l2, l3);
    *(__nv_bfloat162*)(o3 + base)     = H01;
    *(__nv_bfloat162*)(o3 + base + 2) = H23;
    if (wmode == 0) {   // [hi | lo | hi]
        *(__nv_bfloat162*)(o3 + base + Cout)         = L01;
        *(__nv_bfloat162*)(o3 + base + Cout + 2)     = L23;
        *(__nv_bfloat162*)(o3 + base + 2 * Cout)     = H01;
        *(__nv_bfloat162*)(o3 + base + 2 * Cout + 2) = H23;
    } else {            // [hi | hi | lo]
        *(__nv_bfloat162*)(o3 + base + Cout)         = H01;
        *(__nv_bfloat162*)(o3 + base + Cout + 2)     = H23;
        *(__nv_bfloat162*)(o3 + base + 2 * Cout)     = L01;
        *(__nv_bfloat162*)(o3 + base + 2 * Cout + 2) = L23;
    }
}

// ================= pipelined bf16 tensor-core GEMM =================
#define BMT 128
#define BNT 128
#define BKT 32
#define STG 4
#define SPAD 40
#define STILE (BMT * SPAD)

__device__ __forceinline__ void mma_bf16(float* c, const uint32_t* a, const uint32_t* b) {
    asm volatile(
        "mma.sync.aligned.m16n8k16.row.col.f32.bf16.bf16.f32 "
        "{%0,%1,%2,%3}, {%4,%5,%6,%7}, {%8,%9}, {%0,%1,%2,%3};"
        : "+f"(c[0]), "+f"(c[1]), "+f"(c[2]), "+f"(c[3])
        : "r"(a[0]), "r"(a[1]), "r"(a[2]), "r"(a[3]), "r"(b[0]), "r"(b[1]));
}
__device__ __forceinline__ void ldsm4(uint32_t* r, uint32_t addr) {
    asm volatile("ldmatrix.sync.aligned.m8n8.x4.shared.b16 {%0,%1,%2,%3}, [%4];"
                 : "=r"(r[0]), "=r"(r[1]), "=r"(r[2]), "=r"(r[3]) : "r"(addr));
}
__device__ __forceinline__ void cp16(uint32_t saddr, const void* gaddr, int sz) {
    asm volatile("cp.async.cg.shared.global [%0], [%1], 16, %2;"
                 :: "r"(saddr), "l"(gaddr), "r"(sz) : "memory");
}
#define CPCOMMIT() asm volatile("cp.async.commit_group;" ::: "memory")
#define CPWAIT(n)  asm volatile("cp.async.wait_group %0;" :: "n"(n) : "memory")

__global__ __launch_bounds__(256) void gemm_tc(
    const __nv_bfloat16* __restrict__ A, int ldA,
    const __nv_bfloat16* __restrict__ Bm, int ldB,
    float* __restrict__ C, int ldc,
    int N, int K,
    const float* __restrict__ bias, int act, int accum)
{
    extern __shared__ __align__(16) __nv_bfloat16 smem[];
    __nv_bfloat16* As = smem;
    __nv_bfloat16* Bs = smem + STG * STILE;

    const int tid = threadIdx.x;
    const int lane = tid & 31, warp = tid >> 5;
    const int wm = (warp >> 2) * 64;
    const int wn = (warp & 3) * 32;
    const int bm0 = blockIdx.x * BMT;
    const int bn0 = blockIdx.y * BNT;

    float acc[4][4][4];
    #pragma unroll
    for (int i = 0; i < 4; i++)
        #pragma unroll
        for (int j = 0; j < 4; j++)
            #pragma unroll
            for (int f = 0; f < 4; f++) acc[i][j][f] = 0.f;

    const int lrow = tid >> 2;
    const int lc = (tid & 3) * 8;

    auto stage_load = [&](int buf, int k0) {
        __nv_bfloat16* as = As + buf * STILE;
        __nv_bfloat16* bs = Bs + buf * STILE;
        #pragma unroll
        for (int it = 0; it < 2; it++) {
            int r = lrow + it * 64;
            int gk = k0 + lc;
            int kv = (gk < K) ? 16 : 0;
            uint32_t sa = (uint32_t)__cvta_generic_to_shared(as + r * SPAD + lc);
            cp16(sa, A + (size_t)(bm0 + r) * ldA + (kv ? gk : 0), kv);
            int bv = (kv && (bn0 + r) < N) ? 16 : 0;
            uint32_t sb = (uint32_t)__cvta_generic_to_shared(bs + r * SPAD + lc);
            cp16(sb, Bm + (size_t)(bv ? (bn0 + r) : 0) * ldB + (bv ? gk : 0), bv);
        }
    };

    const int nk = (K + BKT - 1) / BKT;
    #pragma unroll
    for (int s = 0; s < STG - 1; s++) {
        if (s < nk) stage_load(s, s * BKT);
        CPCOMMIT();
    }

    const int a_row = wm + (lane & 15);
    const int a_koff = (lane >> 4) * 8;
    const int b_row = wn + (lane & 7) + ((lane >> 4) << 3);
    const int b_koff = ((lane >> 3) & 1) * 8;

    for (int i = 0; i < nk; i++) {
        CPWAIT(STG - 2);
        __syncthreads();
        const __nv_bfloat16* as = As + (i % STG) * STILE;
        const __nv_bfloat16* bs = Bs + (i % STG) * STILE;
        #pragma unroll
        for (int ks = 0; ks < BKT; ks += 16) {
            uint32_t ah[4][4], bh[4][2];
            #pragma unroll
            for (int im = 0; im < 4; im++)
                ldsm4(ah[im], (uint32_t)__cvta_generic_to_shared(
                    as + (a_row + im * 16) * SPAD + ks + a_koff));
            #pragma unroll
            for (int ib = 0; ib < 2; ib++) {
                uint32_t rh[4];
                ldsm4(rh, (uint32_t)__cvta_generic_to_shared(
                    bs + (b_row + ib * 16) * SPAD + ks + b_koff));
                bh[2 * ib][0] = rh[0]; bh[2 * ib][1] = rh[1];
                bh[2 * ib + 1][0] = rh[2]; bh[2 * ib + 1][1] = rh[3];
            }
            #pragma unroll
            for (int im = 0; im < 4; im++)
                #pragma unroll
                for (int in = 0; in < 4; in++)
                    mma_bf16(acc[im][in], ah[im], bh[in]);
        }
        __syncthreads();
        int nx = i + STG - 1;
        if (nx < nk) stage_load(nx % STG, nx * BKT);
        CPCOMMIT();
    }

    #pragma unroll
    for (int im = 0; im < 4; im++) {
        int row0 = bm0 + wm + im * 16 + (lane >> 2);
        #pragma unroll
        for (int in = 0; in < 4; in++) {
            int col = bn0 + wn + in * 8 + 2 * (lane & 3);
            if (col >= N) continue;
            #pragma unroll
            for (int half = 0; half < 2; half++) {
                int row = row0 + half * 8;
                float v0 = acc[im][in][half * 2 + 0];
                float v1 = acc[im][in][half * 2 + 1];
                if (bias) { v0 += bias[col]; v1 += bias[col + 1]; }
                if (act == 1) {
                    v0 = (v0 > 20.f) ? v0 : log1pf(expf(v0));
                    v1 = (v1 > 20.f) ? v1 : log1pf(expf(v1));
                }
                float* cp = C + (size_t)row * ldc + col;
                if (accum) { v0 += cp[0]; v1 += cp[1]; }
                *(float2*)cp = make_float2(v0, v1);
            }
        }
    }
}

// selective scan -> y as A-side 3-section [hi|lo|hi]
__global__ void scan3_k(const float* __restrict__ dt, const float* __restrict__ dbc,
                        const float* __restrict__ xc, const float* __restrict__ xz,
                        const float* __restrict__ Alog, const float* __restrict__ Dp,
                        __nv_bfloat16* __restrict__ y3) {
    int t = blockIdx.x * blockDim.x + threadIdx.x;
    if (t >= B_ * DI_) return;
    int b = t / DI_, d = t % DI_;
    float a[DS_], h[DS_];
    #pragma unroll
    for (int n = 0; n < DS_; n++) { a[n] = -expf(Alog[d * DS_ + n]); h[n] = 0.f; }
    float Dpd = Dp[d];
    for (int s = 0; s < S_; s++) {
        size_t r = (size_t)b * S_ + s;
        float dtv = dt[r * DI_ + d];
        float xv  = xc[r * DI_ + d];
        float zv  = xz[r * XZ_ + DI_ + d];
        const float* bc = dbc + r * DBC_;
        float dx = dtv * xv;
        float yv = 0.f;
        #pragma unroll
        for (int n = 0; n < DS_; n++) {
            float e = expf(dtv * a[n]);
            h[n] = e * h[n] + dx * bc[DR_ + n];
            yv  += h[n] * bc[DR_ + DS_ + n];
        }
        yv += Dpd * xv;
        float sil = zv / (1.f + expf(-zv));
        float o = yv * sil;
        __nv_bfloat16 hh, ll; split_bf(o, hh, ll);
        size_t base = r * 3 * DI_ + d;
        y3[base] = hh; y3[base + DI_] = ll; y3[base + 2 * DI_] = hh;
    }
}

__global__ void loss_row_k(const float* __restrict__ logits, const int* __restrict__ labels,
                           float* __restrict__ rownll) {
    int r = blockIdx.x;
    const float* lr = logits + (size_t)r * V_;
    __shared__ float red[32];
    float m = -INFINITY;
    for (int i = threadIdx.x; i < V_; i += blockDim.x) m = fmaxf(m, lr[i]);
    #pragma unroll
    for (int o = 16; o; o >>= 1) m = fmaxf(m, __shfl_xor_sync(~0u, m, o));
    if ((threadIdx.x & 31) == 0) red[threadIdx.x >> 5] = m;
    __syncthreads();
    if (threadIdx.x == 0) { float v = red[0]; for (int i = 1; i < 8; i++) v = fmaxf(v, red[i]); red[0] = v; }
    __syncthreads();
    m = red[0];
    __syncthreads();
    float sum = 0.f;
    for (int i = threadIdx.x; i < V_; i += blockDim.x) sum += expf(lr[i] - m);
    #pragma unroll
    for (int o = 16; o; o >>= 1) sum += __shfl_xor_sync(~0u, sum, o);
    if ((threadIdx.x & 31) == 0) red[threadIdx.x >> 5] = sum;
    __syncthreads();
    if (threadIdx.x == 0) {
        float v = 0.f;
        for (int i = 0; i < 8; i++) v += red[i];
        int lab = labels[r];
        float nll = 0.f;
        if (lab != -100) nll = (m + logf(v)) - lr[lab];
        rownll[r] = nll;
    }
}

__global__ void loss_red_k(const float* __restrict__ rownll, const int* __restrict__ labels,
                           float* __restrict__ out) {
    __shared__ float rs[32]; __shared__ int rc[32];
    float s = 0.f; int c = 0;
    for (int i = threadIdx.x; i < BS_; i += blockDim.x) {
        s += rownll[i];
        if (labels[i] != -100) c++;
    }
    #pragma unroll
    for (int o = 16; o; o >>= 1) { s += __shfl_xor_sync(~0u, s, o); c += __shfl_xor_sync(~0u, c, o); }
    if ((threadIdx.x & 31) == 0) { rs[threadIdx.x >> 5] = s; rc[threadIdx.x >> 5] = c; }
    __syncthreads();
    if (threadIdx.x == 0) {
        float vs = 0.f; int vc = 0;
        for (int i = 0; i < 8; i++) { vs += rs[i]; vc += rc[i]; }
        if (vc < 1) vc = 1;
        *out = vs / (float)vc;
    }
}

#define GSMEM (2 * STG * STILE * 2)

static void launch_gemm(const __nv_bfloat16* A3, int ldA, const __nv_bfloat16* B3, int ldB,
                        float* C, int ldc, int M, int N, int K3,
                        const float* bias, int act, int accum) {
    dim3 grid(M / BMT, (N + BNT - 1) / BNT);
    gemm_tc<<<grid, 256, GSMEM>>>(A3, ldA, B3, ldB, C, ldc, N, K3, bias, act, accum);
}
static void launch_cvt3(const float* x, __nv_bfloat16* o3, int R, int ldin, int Cout, int wmode) {
    int n4 = R * Cout / 4;
    cvt3_k<<<(n4 + 255) / 256, 256>>>(x, o3, ldin, Cout, n4, wmode);
}

extern "C" void kernel_launch(void* const* d_in, const int* in_sizes, int n_in,
                              void* d_out, int out_size) {
    const int* ids    = (const int*)d_in[0];
    const int* labels = (const int*)d_in[1];
    const float* P[2][12];
    for (int dir = 0; dir < 2; dir++)
        for (int j = 0; j < 12; j++)
            P[dir][j] = (const float*)d_in[2 + dir * 12 + j];
    const float* lm_w = (const float*)d_in[26];
    float* out = (float*)d_out;
    float* logits = out;

    cudaFuncSetAttribute(gemm_tc, cudaFuncAttributeMaxDynamicSharedMemorySize, GSMEM);

    float *h, *xz, *xc, *dbcp, *dt, *rownll;
    __nv_bfloat16 *a3, *d3, *c3, *w3;
    cudaGetSymbolAddress((void**)&h,     g_h);
    cudaGetSymbolAddress((void**)&xz,    g_xz);
    cudaGetSymbolAddress((void**)&xc,    g_xc);
    cudaGetSymbolAddress((void**)&dbcp,  g_dbc);
    cudaGetSymbolAddress((void**)&dt,    g_dt);
    cudaGetSymbolAddress((void**)&rownll, g_rownll);
    cudaGetSymbolAddress((void**)&a3, g_a3);
    cudaGetSymbolAddress((void**)&d3, g_d3);
    cudaGetSymbolAddress((void**)&c3, g_c3);
    cudaGetSymbolAddress((void**)&w3, g_w3);

    for (int dir = 0; dir < 2; dir++) {
        const float* emb   = P[dir][0];
        const float* norm  = P[dir][1];
        const float* inw   = P[dir][2];
        const float* convw = P[dir][3];
        const float* convb = P[dir][4];
        const float* xpw   = P[dir][5];
        const float* dtw   = P[dir][6];
        const float* dtb   = P[dir][7];
        const float* Alog  = P[dir][8];
        const float* Dp    = P[dir][9];
        const float* outw  = P[dir][10];
        const float* fnorm = P[dir][11];

        embed_k<<<BS_, 256>>>(ids, emb, h, dir);

        for (int l = 0; l < L_; l++) {
            rms3_k<<<BS_, 256>>>(h, norm + (size_t)l * DM_, a3, DM_, 0, 0);
            // xz = xn @ inw^T  (K3 = 2304)
            launch_cvt3(inw + (size_t)l * XZ_ * DM_, w3, XZ_, DM_, DM_, 1);
            launch_gemm(a3, 3 * DM_, w3, 3 * DM_, xz, XZ_, BS_, XZ_, 3 * DM_, nullptr, 0, 0);
            // xc = silu(conv(xz[:, :DI]))
            conv3_k<<<(BS_ * DI_ + 255) / 256, 256>>>(xz, convw + (size_t)l * DI_ * KC_,
                                                      convb + (size_t)l * DI_, xc, a3);
            // dbc = xc @ xpw^T  (K3 = 4608)
            launch_cvt3(xpw + (size_t)l * DBC_ * DI_, w3, DBC_, DI_, DI_, 1);
            launch_gemm(a3, 3 * DI_, w3, 3 * DI_, dbcp, DBC_, BS_, DBC_, 3 * DI_, nullptr, 0, 0);
            // dt = softplus(dbc[:, :48] @ dtw^T + dtb)  (K3 = 144)
            launch_cvt3(dbcp, d3, BS_, DBC_, DR_, 0);                       // A-side [hi|lo|hi]
            launch_cvt3(dtw + (size_t)l * DI_ * DR_, w3, DI_, DR_, DR_, 1); // B-side [hi|hi|lo]
            launch_gemm(d3, 3 * DR_, w3, 3 * DR_, dt, DI_, BS_, DI_, 3 * DR_,
                        dtb + (size_t)l * DI_, 1, 0);
            // scan -> y3
            scan3_k<<<(B_ * DI_ + 127) / 128, 128>>>(dt, dbcp, xc, xz,
                                                     Alog + (size_t)l * DI_ * DS_,
                                                     Dp + (size_t)l * DI_, a3);
            // h += y @ outw^T  (K3 = 4608)
            launch_cvt3(outw + (size_t)l * DM_ * DI_, w3, DM_, DI_, DI_, 1);
            launch_gemm(a3, 3 * DI_, w3, 3 * DI_, h, DM_, BS_, DM_, 3 * DI_, nullptr, 0, 1);
        }
        rms3_k<<<BS_, 256>>>(h, fnorm, c3, 2 * DM_, dir ? DM_ : 0, dir);
    }

    launch_cvt3(lm_w, w3, V_, 2 * DM_, 2 * DM_, 1);
    launch_gemm(c3, 3 * 2 * DM_, w3, 3 * 2 * DM_, logits, V_, BS_, V_, 3 * 2 * DM_, nullptr, 0, 0);

    loss_row_k<<<BS_, 256>>>(logits, labels, rownll);
    loss_red_k<<<1, 256>>>(rownll, labels, out + (out_size - 1));
}

// round 8
// speedup vs baseline: 5.3672x; 4.0156x over previous
#include <cuda_runtime.h>
#include <cuda_bf16.h>
#include <math.h>
#include <stdint.h>

#define L_   4
#define DM_  768
#define DI_  1536
#define DS_  16
#define DR_  48
#define KC_  4
#define V_   32000
#define B_   2
#define S_   2048
#define BS_  (B_*S_)
#define XZ_  (2*DI_)
#define DBC_ (DR_+2*DS_)   // 80
#define BD_  (B_*DI_)      // 3072 scan channels
#define SCH  64            // scan chunk length
#define SNG  (S_/SCH)      // 32 chunks

// ---------------- scratch ----------------
__device__ float g_h   [BS_*DM_];
__device__ float g_xz  [BS_*XZ_];
__device__ float g_xc  [BS_*DI_];
__device__ float g_dbc [BS_*DBC_];
__device__ float g_dt  [BS_*DI_];
__device__ float g_rownll[BS_];
__device__ float g_hloc[(size_t)SNG*DS_*BD_];
__device__ float g_hin [(size_t)SNG*DS_*BD_];
__device__ float g_sdt [(size_t)SNG*BD_];
// 3-section bf16-split operands. A-side: [hi|lo|hi], B-side: [hi|hi|lo]
__device__ __nv_bfloat16 g_a3[(size_t)BS_*3*DI_];
__device__ __nv_bfloat16 g_d3[(size_t)BS_*3*DR_];
__device__ __nv_bfloat16 g_c3[(size_t)BS_*3*(2*DM_)];
__device__ __nv_bfloat16 g_w3[(size_t)V_*3*(2*DM_)];

__device__ __forceinline__ void split_bf(float v, __nv_bfloat16& h, __nv_bfloat16& l) {
    h = __float2bfloat16(v);
    l = __float2bfloat16(v - __bfloat162float(h));
}

__global__ void embed_k(const int* __restrict__ ids, const float* __restrict__ emb,
                        float* __restrict__ h, int flip) {
    int r = blockIdx.x;
    int b = r / S_, s = r % S_;
    int s2 = flip ? (S_ - 1 - s) : s;
    int tok = ids[b * S_ + s2];
    const float* e = emb + (size_t)tok * DM_;
    float* o = h + (size_t)r * DM_;
    for (int i = threadIdx.x; i < DM_; i += blockDim.x) o[i] = e[i];
}

// RMSNorm -> A-side 3-section bf16 [hi|lo|hi]
__global__ void rms3_k(const float* __restrict__ x, const float* __restrict__ w,
                       __nv_bfloat16* __restrict__ o3, int Ctot, int off, int flip) {
    int r = blockIdx.x;
    const float* xr = x + (size_t)r * DM_;
    float ss = 0.f;
    for (int i = threadIdx.x; i < DM_; i += blockDim.x) { float v = xr[i]; ss += v * v; }
    __shared__ float red[32];
    #pragma unroll
    for (int o = 16; o; o >>= 1) ss += __shfl_xor_sync(~0u, ss, o);
    if ((threadIdx.x & 31) == 0) red[threadIdx.x >> 5] = ss;
    __syncthreads();
    if (threadIdx.x < 32) {
        float v = (threadIdx.x < (blockDim.x >> 5)) ? red[threadIdx.x] : 0.f;
        #pragma unroll
        for (int o = 16; o; o >>= 1) v += __shfl_xor_sync(~0u, v, o);
        if (threadIdx.x == 0) red[0] = v;
    }
    __syncthreads();
    float scale = rsqrtf(red[0] / (float)DM_ + 1e-5f);
    int ro = r;
    if (flip) { int b = r / S_, s = r % S_; ro = b * S_ + (S_ - 1 - s); }
    size_t base = (size_t)ro * 3 * Ctot + off;
    for (int i = threadIdx.x; i < DM_; i += blockDim.x) {
        float v = xr[i] * scale * w[i];
        __nv_bfloat16 hh, ll; split_bf(v, hh, ll);
        o3[base + i] = hh; o3[base + Ctot + i] = ll; o3[base + 2 * Ctot + i] = hh;
    }
}

// depthwise causal conv + SiLU -> fp32 + A-side [hi|lo|hi]
__global__ void conv3_k(const float* __restrict__ xz, const float* __restrict__ cw,
                        const float* __restrict__ cb, float* __restrict__ xc,
                        __nv_bfloat16* __restrict__ o3) {
    int idx = blockIdx.x * blockDim.x + threadIdx.x;
    if (idx >= BS_ * DI_) return;
    int d = idx % DI_;
    int r = idx / DI_;
    int s = r % S_;
    float acc = cb[d];
    #pragma unroll
    for (int k = 0; k < KC_; k++) {
        int sp = s - (KC_ - 1) + k;
        if (sp >= 0) acc += xz[(size_t)(r - s + sp) * XZ_ + d] * cw[d * KC_ + k];
    }
    float sig = 1.f / (1.f + __expf(-acc));
    float v = acc * sig;
    xc[idx] = v;
    __nv_bfloat16 hh, ll; split_bf(v, hh, ll);
    size_t base = (size_t)r * 3 * DI_ + d;
    o3[base] = hh; o3[base + DI_] = ll; o3[base + 2 * DI_] = hh;
}

// fp32 [R,Cin] (stride ldin) -> first Cout cols -> 3-section bf16
// wmode 0 (A-side): [hi|lo|hi]   wmode 1 (B-side): [hi|hi|lo]
__global__ void cvt3_k(const float* __restrict__ x, __nv_bfloat16* __restrict__ o3,
                       int ldin, int Cout, int n4, int wmode) {
    int i = blockIdx.x * blockDim.x + threadIdx.x;
    if (i >= n4) return;
    int e = i * 4;
    int r = e / Cout, c = e % Cout;
    float4 v = *(const float4*)(x + (size_t)r * ldin + c);
    __nv_bfloat16 h0, h1, h2, h3, l0, l1, l2, l3;
    split_bf(v.x, h0, l0); split_bf(v.y, h1, l1);
    split_bf(v.z, h2, l2); split_bf(v.w, h3, l3);
    size_t base = (size_t)r * 3 * Cout + c;
    __nv_bfloat162 H01(h0, h1), H23(h2, h3), L01(l0, l1), L23(l2, l3);
    *(__nv_bfloat162*)(o3 + base)     = H01;
    *(__nv_bfloat162*)(o3 + base + 2) = H23;
    if (wmode == 0) {
        *(__nv_bfloat162*)(o3 + base + Cout)         = L01;
        *(__nv_bfloat162*)(o3 + base + Cout + 2)     = L23;
        *(__nv_bfloat162*)(o3 + base + 2 * Cout)     = H01;
        *(__nv_bfloat162*)(o3 + base + 2 * Cout + 2) = H23;
    } else {
        *(__nv_bfloat162*)(o3 + base + Cout)         = H01;
        *(__nv_bfloat162*)(o3 + base + Cout + 2)     = H23;
        *(__nv_bfloat162*)(o3 + base + 2 * Cout)     = L01;
        *(__nv_bfloat162*)(o3 + base + 2 * Cout + 2) = L23;
    }
}

// ================= pipelined bf16 tensor-core GEMM: 4 warps, 64x64 per warp =================
#define BMT 128
#define BNT 128
#define BKT 32
#define STG 4
#define SPAD 40
#define STILE (BMT * SPAD)

__device__ __forceinline__ void mma_bf16(float* c, const uint32_t* a, const uint32_t* b) {
    asm volatile(
        "mma.sync.aligned.m16n8k16.row.col.f32.bf16.bf16.f32 "
        "{%0,%1,%2,%3}, {%4,%5,%6,%7}, {%8,%9}, {%0,%1,%2,%3};"
        : "+f"(c[0]), "+f"(c[1]), "+f"(c[2]), "+f"(c[3])
        : "r"(a[0]), "r"(a[1]), "r"(a[2]), "r"(a[3]), "r"(b[0]), "r"(b[1]));
}
__device__ __forceinline__ void ldsm4(uint32_t* r, uint32_t addr) {
    asm volatile("ldmatrix.sync.aligned.m8n8.x4.shared.b16 {%0,%1,%2,%3}, [%4];"
                 : "=r"(r[0]), "=r"(r[1]), "=r"(r[2]), "=r"(r[3]) : "r"(addr));
}
__device__ __forceinline__ void cp16(uint32_t saddr, const void* gaddr, int sz) {
    asm volatile("cp.async.cg.shared.global [%0], [%1], 16, %2;"
                 :: "r"(saddr), "l"(gaddr), "r"(sz) : "memory");
}
#define CPCOMMIT() asm volatile("cp.async.commit_group;" ::: "memory")
#define CPWAIT(n)  asm volatile("cp.async.wait_group %0;" :: "n"(n) : "memory")

__global__ void __launch_bounds__(128, 2) gemm_tc(
    const __nv_bfloat16* __restrict__ A, int ldA,
    const __nv_bfloat16* __restrict__ Bm, int ldB,
    float* __restrict__ C, int ldc,
    int N, int K,
    const float* __restrict__ bias, int act, int accum)
{
    extern __shared__ __align__(16) __nv_bfloat16 smem[];
    __nv_bfloat16* As = smem;
    __nv_bfloat16* Bs = smem + STG * STILE;

    const int tid = threadIdx.x;
    const int lane = tid & 31, warp = tid >> 5;   // 4 warps
    const int wm = (warp >> 1) * 64;              // 0 / 64
    const int wn = (warp & 1) * 64;               // 0 / 64
    const int bm0 = blockIdx.x * BMT;
    const int bn0 = blockIdx.y * BNT;

    float acc[4][8][4];
    #pragma unroll
    for (int i = 0; i < 4; i++)
        #pragma unroll
        for (int j = 0; j < 8; j++)
            #pragma unroll
            for (int f = 0; f < 4; f++) acc[i][j][f] = 0.f;

    const int lrow = tid >> 2;        // 0..31
    const int lc = (tid & 3) * 8;     // 0,8,16,24

    auto stage_load = [&](int buf, int k0) {
        __nv_bfloat16* as = As + buf * STILE;
        __nv_bfloat16* bs = Bs + buf * STILE;
        #pragma unroll
        for (int it = 0; it < 4; it++) {
            int r = lrow + it * 32;
            int gk = k0 + lc;
            int kv = (gk < K) ? 16 : 0;
            uint32_t sa = (uint32_t)__cvta_generic_to_shared(as + r * SPAD + lc);
            cp16(sa, A + (size_t)(bm0 + r) * ldA + (kv ? gk : 0), kv);
            int bv = (kv && (bn0 + r) < N) ? 16 : 0;
            uint32_t sb = (uint32_t)__cvta_generic_to_shared(bs + r * SPAD + lc);
            cp16(sb, Bm + (size_t)(bv ? (bn0 + r) : 0) * ldB + (bv ? gk : 0), bv);
        }
    };

    const int nk = (K + BKT - 1) / BKT;
    #pragma unroll
    for (int s = 0; s < STG - 1; s++) {
        if (s < nk) stage_load(s, s * BKT);
        CPCOMMIT();
    }

    const int a_row = wm + (lane & 15);
    const int a_koff = (lane >> 4) * 8;
    const int b_row = wn + (lane & 7) + ((lane >> 4) << 3);
    const int b_koff = ((lane >> 3) & 1) * 8;

    for (int i = 0; i < nk; i++) {
        CPWAIT(STG - 2);
        __syncthreads();
        const __nv_bfloat16* as = As + (i % STG) * STILE;
        const __nv_bfloat16* bs = Bs + (i % STG) * STILE;
        #pragma unroll
        for (int ks = 0; ks < BKT; ks += 16) {
            uint32_t ah[4][4], bh[8][2];
            #pragma unroll
            for (int im = 0; im < 4; im++)
                ldsm4(ah[im], (uint32_t)__cvta_generic_to_shared(
                    as + (a_row + im * 16) * SPAD + ks + a_koff));
            #pragma unroll
            for (int ib = 0; ib < 4; ib++) {
                uint32_t rh[4];
                ldsm4(rh, (uint32_t)__cvta_generic_to_shared(
                    bs + (b_row + ib * 16) * SPAD + ks + b_koff));
                bh[2 * ib][0] = rh[0]; bh[2 * ib][1] = rh[1];
                bh[2 * ib + 1][0] = rh[2]; bh[2 * ib + 1][1] = rh[3];
            }
            #pragma unroll
            for (int im = 0; im < 4; im++)
                #pragma unroll
                for (int in = 0; in < 8; in++)
                    mma_bf16(acc[im][in], ah[im], bh[in]);
        }
        __syncthreads();
        int nx = i + STG - 1;
        if (nx < nk) stage_load(nx % STG, nx * BKT);
        CPCOMMIT();
    }

    #pragma unroll
    for (int im = 0; im < 4; im++) {
        int row0 = bm0 + wm + im * 16 + (lane >> 2);
        #pragma unroll
        for (int in = 0; in < 8; in++) {
            int col = bn0 + wn + in * 8 + 2 * (lane & 3);
            if (col >= N) continue;
            #pragma unroll
            for (int half = 0; half < 2; half++) {
                int row = row0 + half * 8;
                float v0 = acc[im][in][half * 2 + 0];
                float v1 = acc[im][in][half * 2 + 1];
                if (bias) { v0 += bias[col]; v1 += bias[col + 1]; }
                if (act == 1) {
                    v0 = (v0 > 20.f) ? v0 : log1pf(expf(v0));
                    v1 = (v1 > 20.f) ? v1 : log1pf(expf(v1));
                }
                float* cp = C + (size_t)row * ldc + col;
                if (accum) { v0 += cp[0]; v1 += cp[1]; }
                *(float2*)cp = make_float2(v0, v1);
            }
        }
    }
}

// ================= chunked parallel scan =================
// Pass A: per (chunk, b, d): local scan from h=0 -> hloc[16], sum(dt)
__global__ void scanA_k(const float* __restrict__ dt, const float* __restrict__ dbc,
                        const float* __restrict__ xc, const float* __restrict__ Alog,
                        float* __restrict__ hloc, float* __restrict__ sdt) {
    int idx = blockIdx.x * blockDim.x + threadIdx.x;
    if (idx >= SNG * BD_) return;
    int c = idx / BD_;
    int t = idx % BD_;
    int b = t / DI_, d = t % DI_;
    float a[DS_], h[DS_];
    #pragma unroll
    for (int n = 0; n < DS_; n++) { a[n] = -expf(Alog[d * DS_ + n]); h[n] = 0.f; }
    float sum_dt = 0.f;
    int s0 = c * SCH;
    for (int s = s0; s < s0 + SCH; s++) {
        size_t r = (size_t)b * S_ + s;
        float dtv = dt[r * DI_ + d];
        float xv  = xc[r * DI_ + d];
        const float* bc = dbc + r * DBC_;
        float dx = dtv * xv;
        sum_dt += dtv;
        #pragma unroll
        for (int n = 0; n < DS_; n++)
            h[n] = __expf(dtv * a[n]) * h[n] + dx * bc[DR_ + n];
    }
    #pragma unroll
    for (int n = 0; n < DS_; n++)
        hloc[((size_t)c * DS_ + n) * BD_ + t] = h[n];
    sdt[(size_t)c * BD_ + t] = sum_dt;
}

// Pass B: per (b, d): compose chunks sequentially -> hin per chunk
__global__ void scanB_k(const float* __restrict__ hloc, const float* __restrict__ sdt,
                        const float* __restrict__ Alog, float* __restrict__ hin) {
    int t = blockIdx.x * blockDim.x + threadIdx.x;
    if (t >= BD_) return;
    int d = t % DI_;
    float a[DS_], h[DS_];
    #pragma unroll
    for (int n = 0; n < DS_; n++) { a[n] = -expf(Alog[d * DS_ + n]); h[n] = 0.f; }
    for (int c = 0; c < SNG; c++) {
        #pragma unroll
        for (int n = 0; n < DS_; n++)
            hin[((size_t)c * DS_ + n) * BD_ + t] = h[n];
        float sd = sdt[(size_t)c * BD_ + t];
        #pragma unroll
        for (int n = 0; n < DS_; n++)
            h[n] = __expf(a[n] * sd) * h[n] + hloc[((size_t)c * DS_ + n) * BD_ + t];
    }
}

// Pass C: per (chunk, b, d): replay with correct h_in, emit y3 (fused Dp + silu(z))
__global__ void scanC_k(const float* __restrict__ dt, const float* __restrict__ dbc,
                        const float* __restrict__ xc, const float* __restrict__ xz,
                        const float* __restrict__ Alog, const float* __restrict__ Dp,
                        const float* __restrict__ hin, __nv_bfloat16* __restrict__ y3) {
    int idx = blockIdx.x * blockDim.x + threadIdx.x;
    if (idx >= SNG * BD_) return;
    int c = idx / BD_;
    int t = idx % BD_;
    int b = t / DI_, d = t % DI_;
    float a[DS_], h[DS_];
    #pragma unroll
    for (int n = 0; n < DS_; n++) {
        a[n] = -expf(Alog[d * DS_ + n]);
        h[n] = hin[((size_t)c * DS_ + n) * BD_ + t];
    }
    float Dpd = Dp[d];
    int s0 = c * SCH;
    for (int s = s0; s < s0 + SCH; s++) {
        size_t r = (size_t)b * S_ + s;
        float dtv = dt[r * DI_ + d];
        float xv  = xc[r * DI_ + d];
        float zv  = xz[r * XZ_ + DI_ + d];
        const float* bc = dbc + r * DBC_;
        float dx = dtv * xv;
        float yv = 0.f;
        #pragma unroll
        for (int n = 0; n < DS_; n++) {
            h[n] = __expf(dtv * a[n]) * h[n] + dx * bc[DR_ + n];
            yv  += h[n] * bc[DR_ + DS_ + n];
        }
        yv += Dpd * xv;
        float sil = zv / (1.f + __expf(-zv));
        float o = yv * sil;
        __nv_bfloat16 hh, ll; split_bf(o, hh, ll);
        size_t base = r * 3 * DI_ + d;
        y3[base] = hh; y3[base + DI_] = ll; y3[base + 2 * DI_] = hh;
    }
}

__global__ void loss_row_k(const float* __restrict__ logits, const int* __restrict__ labels,
                           float* __restrict__ rownll) {
    int r = blockIdx.x;
    const float* lr = logits + (size_t)r * V_;
    __shared__ float red[32];
    float m = -INFINITY;
    for (int i = threadIdx.x; i < V_; i += blockDim.x) m = fmaxf(m, lr[i]);
    #pragma unroll
    for (int o = 16; o; o >>= 1) m = fmaxf(m, __shfl_xor_sync(~0u, m, o));
    if ((threadIdx.x & 31) == 0) red[threadIdx.x >> 5] = m;
    __syncthreads();
    if (threadIdx.x == 0) { float v = red[0]; for (int i = 1; i < 8; i++) v = fmaxf(v, red[i]); red[0] = v; }
    __syncthreads();
    m = red[0];
    __syncthreads();
    float sum = 0.f;
    for (int i = threadIdx.x; i < V_; i += blockDim.x) sum += __expf(lr[i] - m);
    #pragma unroll
    for (int o = 16; o; o >>= 1) sum += __shfl_xor_sync(~0u, sum, o);
    if ((threadIdx.x & 31) == 0) red[threadIdx.x >> 5] = sum;
    __syncthreads();
    if (threadIdx.x == 0) {
        float v = 0.f;
        for (int i = 0; i < 8; i++) v += red[i];
        int lab = labels[r];
        float nll = 0.f;
        if (lab != -100) nll = (m + logf(v)) - lr[lab];
        rownll[r] = nll;
    }
}

__global__ void loss_red_k(const float* __restrict__ rownll, const int* __restrict__ labels,
                           float* __restrict__ out) {
    __shared__ float rs[32]; __shared__ int rc[32];
    float s = 0.f; int c = 0;
    for (int i = threadIdx.x; i < BS_; i += blockDim.x) {
        s += rownll[i];
        if (labels[i] != -100) c++;
    }
    #pragma unroll
    for (int o = 16; o; o >>= 1) { s += __shfl_xor_sync(~0u, s, o); c += __shfl_xor_sync(~0u, c, o); }
    if ((threadIdx.x & 31) == 0) { rs[threadIdx.x >> 5] = s; rc[threadIdx.x >> 5] = c; }
    __syncthreads();
    if (threadIdx.x == 0) {
        float vs = 0.f; int vc = 0;
        for (int i = 0; i < 8; i++) { vs += rs[i]; vc += rc[i]; }
        if (vc < 1) vc = 1;
        *out = vs / (float)vc;
    }
}

#define GSMEM (2 * STG * STILE * 2)

static void launch_gemm(const __nv_bfloat16* A3, int ldA, const __nv_bfloat16* B3, int ldB,
                        float* C, int ldc, int M, int N, int K3,
                        const float* bias, int act, int accum) {
    dim3 grid(M / BMT, (N + BNT - 1) / BNT);
    gemm_tc<<<grid, 128, GSMEM>>>(A3, ldA, B3, ldB, C, ldc, N, K3, bias, act, accum);
}
static void launch_cvt3(const float* x, __nv_bfloat16* o3, int R, int ldin, int Cout, int wmode) {
    int n4 = R * Cout / 4;
    cvt3_k<<<(n4 + 255) / 256, 256>>>(x, o3, ldin, Cout, n4, wmode);
}

extern "C" void kernel_launch(void* const* d_in, const int* in_sizes, int n_in,
                              void* d_out, int out_size) {
    const int* ids    = (const int*)d_in[0];
    const int* labels = (const int*)d_in[1];
    const float* P[2][12];
    for (int dir = 0; dir < 2; dir++)
        for (int j = 0; j < 12; j++)
            P[dir][j] = (const float*)d_in[2 + dir * 12 + j];
    const float* lm_w = (const float*)d_in[26];
    float* out = (float*)d_out;
    float* logits = out;

    cudaFuncSetAttribute(gemm_tc, cudaFuncAttributeMaxDynamicSharedMemorySize, GSMEM);

    float *h, *xz, *xc, *dbcp, *dt, *rownll, *hloc, *hin, *sdt;
    __nv_bfloat16 *a3, *d3, *c3, *w3;
    cudaGetSymbolAddress((void**)&h,     g_h);
    cudaGetSymbolAddress((void**)&xz,    g_xz);
    cudaGetSymbolAddress((void**)&xc,    g_xc);
    cudaGetSymbolAddress((void**)&dbcp,  g_dbc);
    cudaGetSymbolAddress((void**)&dt,    g_dt);
    cudaGetSymbolAddress((void**)&rownll, g_rownll);
    cudaGetSymbolAddress((void**)&hloc,  g_hloc);
    cudaGetSymbolAddress((void**)&hin,   g_hin);
    cudaGetSymbolAddress((void**)&sdt,   g_sdt);
    cudaGetSymbolAddress((void**)&a3, g_a3);
    cudaGetSymbolAddress((void**)&d3, g_d3);
    cudaGetSymbolAddress((void**)&c3, g_c3);
    cudaGetSymbolAddress((void**)&w3, g_w3);

    for (int dir = 0; dir < 2; dir++) {
        const float* emb   = P[dir][0];
        const float* norm  = P[dir][1];
        const float* inw   = P[dir][2];
        const float* convw = P[dir][3];
        const float* convb = P[dir][4];
        const float* xpw   = P[dir][5];
        const float* dtw   = P[dir][6];
        const float* dtb   = P[dir][7];
        const float* Alog  = P[dir][8];
        const float* Dp    = P[dir][9];
        const float* outw  = P[dir][10];
        const float* fnorm = P[dir][11];

        embed_k<<<BS_, 256>>>(ids, emb, h, dir);

        for (int l = 0; l < L_; l++) {
            rms3_k<<<BS_, 256>>>(h, norm + (size_t)l * DM_, a3, DM_, 0, 0);
            // xz = xn @ inw^T  (K3 = 2304)
            launch_cvt3(inw + (size_t)l * XZ_ * DM_, w3, XZ_, DM_, DM_, 1);
            launch_gemm(a3, 3 * DM_, w3, 3 * DM_, xz, XZ_, BS_, XZ_, 3 * DM_, nullptr, 0, 0);
            // xc = silu(conv(xz[:, :DI]))
            conv3_k<<<(BS_ * DI_ + 255) / 256, 256>>>(xz, convw + (size_t)l * DI_ * KC_,
                                                      convb + (size_t)l * DI_, xc, a3);
            // dbc = xc @ xpw^T  (K3 = 4608)
            launch_cvt3(xpw + (size_t)l * DBC_ * DI_, w3, DBC_, DI_, DI_, 1);
            launch_gemm(a3, 3 * DI_, w3, 3 * DI_, dbcp, DBC_, BS_, DBC_, 3 * DI_, nullptr, 0, 0);
            // dt = softplus(dbc[:, :48] @ dtw^T + dtb)  (K3 = 144)
            launch_cvt3(dbcp, d3, BS_, DBC_, DR_, 0);
            launch_cvt3(dtw + (size_t)l * DI_ * DR_, w3, DI_, DR_, DR_, 1);
            launch_gemm(d3, 3 * DR_, w3, 3 * DR_, dt, DI_, BS_, DI_, 3 * DR_,
                        dtb + (size_t)l * DI_, 1, 0);
            // chunked scan -> y3
            const float* Al = Alog + (size_t)l * DI_ * DS_;
            scanA_k<<<(SNG * BD_ + 127) / 128, 128>>>(dt, dbcp, xc, Al, hloc, sdt);
            scanB_k<<<(BD_ + 127) / 128, 128>>>(hloc, sdt, Al, hin);
            scanC_k<<<(SNG * BD_ + 127) / 128, 128>>>(dt, dbcp, xc, xz, Al,
                                                      Dp + (size_t)l * DI_, hin, a3);
            // h += y @ outw^T  (K3 = 4608)
            launch_cvt3(outw + (size_t)l * DM_ * DI_, w3, DM_, DI_, DI_, 1);
            launch_gemm(a3, 3 * DI_, w3, 3 * DI_, h, DM_, BS_, DM_, 3 * DI_, nullptr, 0, 1);
        }
        rms3_k<<<BS_, 256>>>(h, fnorm, c3, 2 * DM_, dir ? DM_ : 0, dir);
    }

    launch_cvt3(lm_w, w3, V_, 2 * DM_, 2 * DM_, 1);
    launch_gemm(c3, 3 * 2 * DM_, w3, 3 * 2 * DM_, logits, V_, BS_, V_, 3 * 2 * DM_, nullptr, 0, 0);

    loss_row_k<<<BS_, 256>>>(logits, labels, rownll);
    loss_red_k<<<1, 256>>>(rownll, labels, out + (out_size - 1));
}